// round 3
// baseline (speedup 1.0000x reference)
#include <cuda_runtime.h>
#include <cuda_bf16.h>
#include <cstdint>
#include <math.h>

// Problem: B=128, T=512, I=64, H=512, C=10. LSTM -> last hidden -> linear.
#define BB   128
#define TT   512
#define II   64
#define HH   512
#define CC   10

#define NBLOCKS  128
#define NTHREADS 256
#define NBH      4           // hidden units per block
#define ROWS     16          // 4 gates * NBH rows per block

// ---------------- device globals (allocation-free scratch) ----------------
__device__ __align__(256) float g_xT[TT * II * BB];   // [t][i][b]  16 MB
__device__ __align__(256) float g_h[2][HH * BB];      // h transposed [n][b], dbl buffered
__device__ unsigned g_count = 0;
__device__ unsigned g_epoch = 0;

// ---------------- shared memory layout (floats) ----------------
// w_s  : [576][16]  = 9216 floats (resident all kernel)
// a/red: union: A dbl buf 2*[64][128] = 16384 floats == red [8][16][128]
// bias : [16]
#define W_OFF   0
#define A_OFF   9216
#define BI_OFF  (A_OFF + 16384)
#define SMEM_FLOATS (BI_OFF + 16)
#define SMEM_BYTES  (SMEM_FLOATS * 4)

// ---------------- PTX helpers ----------------
__device__ __forceinline__ unsigned long long dup_f32(float w) {
    unsigned long long d; unsigned u = __float_as_uint(w);
    asm("mov.b64 %0, {%1, %1};" : "=l"(d) : "r"(u));
    return d;
}
__device__ __forceinline__ void ffma2(unsigned long long& a, unsigned long long x,
                                      unsigned long long y) {
    asm("fma.rn.f32x2 %0, %1, %2, %0;" : "+l"(a) : "l"(x), "l"(y));
}
__device__ __forceinline__ void cp16(uint32_t dst, const float* src) {
    asm volatile("cp.async.cg.shared.global [%0], [%1], 16;" :: "r"(dst), "l"(src));
}

// stage one 64x128 float chunk (32 KB) into smem buffer, 8 x 16B per thread
__device__ __forceinline__ void stage_chunk(uint32_t dst, const float* src, int tid) {
#pragma unroll
    for (int p = 0; p < 8; ++p) {
        int o = (tid + p * NTHREADS) * 4;
        cp16(dst + (uint32_t)o * 4u, src + o);
    }
    asm volatile("cp.async.commit_group;");
}

// grid-wide barrier: all 128 blocks co-resident (1/SM on 148 SMs)
__device__ __forceinline__ void grid_sync() {
    __threadfence();
    __syncthreads();
    if (threadIdx.x == 0) {
        unsigned e = *((volatile unsigned*)&g_epoch);
        unsigned prev = atomicAdd(&g_count, 1);
        if (prev == NBLOCKS - 1) {
            g_count = 0;
            __threadfence();
            *((volatile unsigned*)&g_epoch) = e + 1;
        } else {
            while (*((volatile unsigned*)&g_epoch) == e) { __nanosleep(64); }
        }
    }
    __syncthreads();
}

__device__ __forceinline__ float sigmoidf_(float x) {
    return 1.0f / (1.0f + expf(-x));
}

// ---------------- prologue: xT[t][i][b] = x[b][0][t][i] ----------------
__global__ void __launch_bounds__(256) xpose_kernel(const float* __restrict__ x) {
    __shared__ float tile[64][129];
    const int t = blockIdx.x;
    const int tid = threadIdx.x;
#pragma unroll
    for (int p = 0; p < 8; ++p) {
        int idx = tid + p * 256;           // float4 id, 0..2047
        int b = idx >> 4, q = idx & 15;
        float4 v = *(const float4*)(x + (size_t)b * (TT * II) + (size_t)t * II + q * 4);
        tile[q * 4 + 0][b] = v.x;
        tile[q * 4 + 1][b] = v.y;
        tile[q * 4 + 2][b] = v.z;
        tile[q * 4 + 3][b] = v.w;
    }
    __syncthreads();
    float* dst = g_xT + (size_t)t * (II * BB);
#pragma unroll
    for (int p = 0; p < 8; ++p) {
        int f = tid + p * 256;             // output float4 id
        int i = f >> 5;
        int b0 = (f & 31) * 4;
        float4 v = make_float4(tile[i][b0], tile[i][b0 + 1], tile[i][b0 + 2], tile[i][b0 + 3]);
        *(float4*)(dst + (size_t)f * 4) = v;
    }
}

// ---------------- persistent LSTM ----------------
__global__ void __launch_bounds__(NTHREADS, 1)
lstm_kernel(const float* __restrict__ W_ih, const float* __restrict__ W_hh,
            const float* __restrict__ b_ih, const float* __restrict__ b_hh,
            const float* __restrict__ W_cls, const float* __restrict__ b_cls,
            float* __restrict__ out)
{
    extern __shared__ float smem[];
    float* w_s    = smem + W_OFF;
    float* a_sm   = smem + A_OFF;     // also red[] after last chunk
    float* bias_s = smem + BI_OFF;

    const int tid  = threadIdx.x;
    const int blk  = blockIdx.x;
    const int kp   = tid >> 5;        // warp id = k partition 0..7
    const int lane = tid & 31;
    const int wid  = kp;
    const int bgrp = lane >> 1;       // 16 groups of 8 batch columns
    const int rgrp = lane & 1;        // 2 groups of 8 rows

    // ---- load weight slice [576 k][16 rows] into smem, once ----
    for (int idx = tid; idx < (HH + II) * ROWS; idx += NTHREADS) {
        int k = idx >> 4, r = idx & 15;
        int gate = r >> 2, nl = r & 3;
        int grow = gate * HH + blk * NBH + nl;
        w_s[idx] = (k < HH) ? W_hh[(size_t)grow * HH + k]
                            : W_ih[(size_t)grow * II + (k - HH)];
    }
    if (tid < ROWS) {
        int gate = tid >> 2, nl = tid & 3;
        int grow = gate * HH + blk * NBH + nl;
        bias_s[tid] = b_ih[grow] + b_hh[grow];
    }
    // zero our slice of h0
    for (int idx = tid; idx < NBH * BB; idx += NTHREADS)
        g_h[0][blk * (NBH * BB) + idx] = 0.0f;

    // cell state: 2 elements per thread: e = 2*tid, 2*tid+1  -> (nl, b)
    float c0 = 0.0f, c1 = 0.0f;
    const int e0 = 2 * tid;
    const int nl_c = e0 >> 7;         // same for both elements
    const int b_c  = e0 & 127;

    grid_sync();                      // h0 + weights visible everywhere

    const uint32_t a_base = (uint32_t)__cvta_generic_to_shared(a_sm);

    for (int t = 0; t < TT; ++t) {
        const int cur = t & 1, nxt = cur ^ 1;
        const float* hsrc = g_h[cur];
        const float* xsrc = g_xT + (size_t)t * (II * BB);

        // prefetch chunk 0 (h rows 0..63) into buffer 0
        stage_chunk(a_base, hsrc, tid);

        unsigned long long acc[8][4];
#pragma unroll
        for (int r = 0; r < 8; ++r) { acc[r][0]=0ull; acc[r][1]=0ull; acc[r][2]=0ull; acc[r][3]=0ull; }

        // 9 chunks: 8 over h (K=512), 1 over x_t (K=64)
        for (int c = 0; c <= 8; ++c) {
            __syncthreads();   // compute on buffer (c+1)&1 finished -> safe to overwrite
            if (c < 8) {
                const float* src = (c < 7) ? (hsrc + (c + 1) * (64 * BB)) : xsrc;
                stage_chunk(a_base + (uint32_t)(((c + 1) & 1) * 64 * BB * 4), src, tid);
                asm volatile("cp.async.wait_group 1;");
            } else {
                asm volatile("cp.async.wait_group 0;");
            }
            __syncthreads();   // chunk c fully staged, visible to all

            const float* ab = a_sm + (c & 1) * (64 * BB);
            const float* wb = w_s + c * 64 * ROWS;
#pragma unroll
            for (int u = 0; u < 8; ++u) {
                const int kl = u * 8 + kp;
                const float* ar = ab + kl * BB + bgrp * 8;
                ulonglong2 h01 = *(const ulonglong2*)(ar);
                ulonglong2 h23 = *(const ulonglong2*)(ar + 4);
                const float* wr = wb + kl * ROWS + rgrp * 8;
                float4 w0 = *(const float4*)(wr);
                float4 w1 = *(const float4*)(wr + 4);
                float wv[8] = {w0.x, w0.y, w0.z, w0.w, w1.x, w1.y, w1.z, w1.w};
#pragma unroll
                for (int r = 0; r < 8; ++r) {
                    unsigned long long wd = dup_f32(wv[r]);
                    ffma2(acc[r][0], h01.x, wd);
                    ffma2(acc[r][1], h01.y, wd);
                    ffma2(acc[r][2], h23.x, wd);
                    ffma2(acc[r][3], h23.y, wd);
                }
            }
        }

        __syncthreads();   // all compute done before red overwrites A buffers

        // write k-split partials: red[kp][r][b] aliased on a_sm
#pragma unroll
        for (int r = 0; r < 8; ++r) {
            float* rr = a_sm + kp * (ROWS * BB) + (rgrp * 8 + r) * BB + bgrp * 8;
#pragma unroll
            for (int p = 0; p < 4; ++p)
                *(unsigned long long*)(rr + p * 2) = acc[r][p];
        }
        __syncthreads();

        // fused reduce + gates + state update: 2 elements per thread
        float hv[2];
#pragma unroll
        for (int e = 0; e < 2; ++e) {
            const int b = b_c + e;
            float s[4];
#pragma unroll
            for (int gate = 0; gate < 4; ++gate) {
                const int r = gate * 4 + nl_c;
                float acc_s = bias_s[r];
#pragma unroll
                for (int q = 0; q < 8; ++q)
                    acc_s += a_sm[q * (ROWS * BB) + r * BB + b];
                s[gate] = acc_s;
            }
            float ig = sigmoidf_(s[0]);
            float fg = sigmoidf_(s[1]);
            float gg = tanhf(s[2]);
            float og = sigmoidf_(s[3]);
            float& cc = e ? c1 : c0;
            cc = fg * cc + ig * gg;
            hv[e] = og * tanhf(cc);
        }
        // h write: transposed layout, coalesced-ish (2 floats per thread)
        float* hd = g_h[nxt] + (blk * NBH + nl_c) * BB + b_c;
        hd[0] = hv[0];
        hd[1] = hv[1];

        grid_sync();
    }

    // ---------------- epilogue: out[b][cl] = h_T . W_cls[cl] + b_cls ----------------
    // final h is in g_h[TT & 1 ^ 1] = g_h[0]
    {
        const float* hf = g_h[0];
        const int b = blk;
        float h0v = hf[(size_t)tid * BB + b];
        float h1v = hf[(size_t)(tid + 256) * BB + b];
        float* wred = a_sm;  // reuse smem
#pragma unroll 1
        for (int cl = 0; cl < CC; ++cl) {
            float s = h0v * W_cls[(size_t)cl * HH + tid]
                    + h1v * W_cls[(size_t)cl * HH + tid + 256];
#pragma unroll
            for (int off = 16; off; off >>= 1)
                s += __shfl_xor_sync(0xFFFFFFFFu, s, off);
            if (lane == 0) wred[cl * 8 + wid] = s;
        }
        __syncthreads();
        if (tid < CC) {
            float s = 0.0f;
#pragma unroll
            for (int w = 0; w < 8; ++w) s += wred[tid * 8 + w];
            out[b * CC + tid] = s + b_cls[tid];
        }
    }
}

// ---------------- launch ----------------
extern "C" void kernel_launch(void* const* d_in, const int* in_sizes, int n_in,
                              void* d_out, int out_size) {
    const float* x     = (const float*)d_in[0];
    const float* W_ih  = (const float*)d_in[1];
    const float* W_hh  = (const float*)d_in[2];
    const float* b_ih  = (const float*)d_in[3];
    const float* b_hh  = (const float*)d_in[4];
    const float* W_cls = (const float*)d_in[5];
    const float* b_cls = (const float*)d_in[6];
    float* out = (float*)d_out;

    cudaFuncSetAttribute(lstm_kernel, cudaFuncAttributeMaxDynamicSharedMemorySize, SMEM_BYTES);

    xpose_kernel<<<TT, 256>>>(x);
    lstm_kernel<<<NBLOCKS, NTHREADS, SMEM_BYTES>>>(W_ih, W_hh, b_ih, b_hh, W_cls, b_cls, out);
}